// round 4
// baseline (speedup 1.0000x reference)
#include <cuda_runtime.h>

#define PI_F 3.14159265358979323846f

static __device__ __forceinline__ void cmul(float ar,float ai,float br,float bi,float&cr,float&ci){
  cr = ar*br - ai*bi; ci = ar*bi + ai*br;
}

// DFT-8 (unscaled, e^{-2pi i mq/8}) on 8 complex values in registers.
static __device__ __forceinline__ void dft8(float xr[8], float xi[8]) {
  const float C = 0.70710678118654752440f;
  float u0r=xr[0]+xr[4], u0i=xi[0]+xi[4];
  float u1r=xr[0]-xr[4], u1i=xi[0]-xi[4];
  float u2r=xr[2]+xr[6], u2i=xi[2]+xi[6];
  float u3r=xr[2]-xr[6], u3i=xi[2]-xi[6];
  float E0r=u0r+u2r, E0i=u0i+u2i;
  float E1r=u1r+u3i, E1i=u1i-u3r;
  float E2r=u0r-u2r, E2i=u0i-u2i;
  float E3r=u1r-u3i, E3i=u1i+u3r;
  float v0r=xr[1]+xr[5], v0i=xi[1]+xi[5];
  float v1r=xr[1]-xr[5], v1i=xi[1]-xi[5];
  float v2r=xr[3]+xr[7], v2i=xi[3]+xi[7];
  float v3r=xr[3]-xr[7], v3i=xi[3]-xi[7];
  float O0r=v0r+v2r, O0i=v0i+v2i;
  float O1r=v1r+v3i, O1i=v1i-v3r;
  float O2r=v0r-v2r, O2i=v0i-v2i;
  float O3r=v1r-v3i, O3i=v1i+v3r;
  float w1r=C*(O1r+O1i), w1i=C*(O1i-O1r);
  float w2r=O2i,          w2i=-O2r;
  float w3r=C*(O3i-O3r),  w3i=-C*(O3r+O3i);
  xr[0]=E0r+O0r; xi[0]=E0i+O0i;
  xr[4]=E0r-O0r; xi[4]=E0i-O0i;
  xr[1]=E1r+w1r; xi[1]=E1i+w1i;
  xr[5]=E1r-w1r; xi[5]=E1i-w1i;
  xr[2]=E2r+w2r; xi[2]=E2i+w2i;
  xr[6]=E2r-w2r; xi[6]=E2i-w2i;
  xr[3]=E3r+w3r; xi[3]=E3i+w3i;
  xr[7]=E3r-w3r; xi[7]=E3i-w3i;
}

__global__ void __launch_bounds__(128, 8)
feat_kernel(const float* __restrict__ x, float* __restrict__ out)
{
  __shared__ float  s_sig[2048];
  __shared__ float2 s_d[1088];   // 1024 complex, pad i -> i + (i>>4); k-layout pad k + (k>>6)
  __shared__ float  scr[20];
  __shared__ int sh_np, sh_nv, sh_p0, sh_v0, sh_vl, sh_v1, sh_li, sh_ri;

  const int tid  = threadIdx.x;   // 0..127
  const int lane = tid & 31;
  const int warp = tid >> 5;      // 0..3
  const size_t row = blockIdx.x;
  const float* xp = x + row * 2048;

  // ---- load row (coalesced float4, 4 per thread) ----
  {
    const float4* xv = (const float4*)xp;
    float4* sv = (float4*)s_sig;
    #pragma unroll
    for (int c=0;c<4;c++) sv[tid + (c<<7)] = xv[tid + (c<<7)];
  }
  if (tid==0){
    sh_np=0; sh_nv=0; sh_p0=0x7fffffff; sh_v0=0x7fffffff;
    sh_vl=-1; sh_v1=0x7fffffff; sh_li=0x7fffffff; sh_ri=-1;
  }
  __syncthreads();

  // ============ 1024-pt complex FFT of z_n = x[2n] + i x[2n+1], DIF 8,8,8,2 ============
  float ar[8], ai[8];
  float mx=-3.0e38f, mn=3.0e38f, sm=0.f, sq=0.f;

  // ---- pass 1: L=1024, stride 128 ----
  {
    const float2* zin = (const float2*)s_sig;
    #pragma unroll
    for (int m=0;m<8;m++){
      float2 z = zin[tid + (m<<7)];
      ar[m]=z.x; ai[m]=z.y;
      mx=fmaxf(mx,fmaxf(z.x,z.y)); mn=fminf(mn,fminf(z.x,z.y));
      sm += z.x + z.y; sq += z.x*z.x + z.y*z.y;
    }
    dft8(ar, ai);
    float sn,cs; __sincosf(-2.f*PI_F*(float)tid*(1.f/1024.f), &sn, &cs);
    const int ob = tid + (tid>>4);          // pad16; q offset = 136
    s_d[ob] = make_float2(ar[0], ai[0]);
    float wr=cs, wi=sn;
    #pragma unroll
    for (int q=1;q<8;q++){
      float rr,ii; cmul(ar[q],ai[q],wr,wi,rr,ii);
      s_d[ob + 136*q] = make_float2(rr,ii);
      float nr,ni; cmul(wr,wi,cs,sn,nr,ni); wr=nr; wi=ni;
    }
  }
  __syncthreads();

  // ---- pass 2: L=128, stride 16; sub = tid>>4, tt = tid&15; padded idx = 136sub+tt+17m ----
  {
    const int sub = tid>>4, tt = tid&15;
    const int ob = 136*sub + tt;
    #pragma unroll
    for (int m=0;m<8;m++){ float2 v = s_d[ob + 17*m]; ar[m]=v.x; ai[m]=v.y; }
    dft8(ar, ai);
    float sn,cs; __sincosf(-2.f*PI_F*(float)tt*(1.f/128.f), &sn, &cs);
    float wr=cs, wi=sn;
    s_d[ob] = make_float2(ar[0], ai[0]);
    #pragma unroll
    for (int q=1;q<8;q++){
      float rr,ii; cmul(ar[q],ai[q],wr,wi,rr,ii);
      s_d[ob + 17*q] = make_float2(rr,ii);
      float nr,ni; cmul(wr,wi,cs,sn,nr,ni); wr=nr; wi=ni;
    }
  }
  __syncthreads();

  // ---- pass 3: L=16, stride 2; tt = tid>>6, sid = tid&63; padded idx = 17sid+tt+2m ----
  {
    const int tt = tid>>6, sid = tid&63;
    const int ob = 17*sid + tt;
    #pragma unroll
    for (int m=0;m<8;m++){ float2 v = s_d[ob + 2*m]; ar[m]=v.x; ai[m]=v.y; }
    dft8(ar, ai);
    float sn,cs; __sincosf(-2.f*PI_F*(float)tt*(1.f/16.f), &sn, &cs);
    float wr=cs, wi=sn;
    s_d[ob] = make_float2(ar[0], ai[0]);
    #pragma unroll
    for (int q=1;q<8;q++){
      float rr,ii; cmul(ar[q],ai[q],wr,wi,rr,ii);
      s_d[ob + 2*q] = make_float2(rr,ii);
      float nr,ni; cmul(wr,wi,cs,sn,nr,ni); wr=nr; wi=ni;
    }
  }
  __syncthreads();

  // ---- pass 4: radix-2 on pairs (2j,2j+1); results re-stored in NATURAL k order ----
  // position p = (m1<<7)|(m2<<4)|(m3<<1)|t holds frequency k = (t<<9)|(m3<<6)|(m2<<3)|m1
  float zr[8], zi[8];
  #pragma unroll
  for (int c=0;c<4;c++){
    int j = tid + (c<<7);
    int p = 2*j;
    int ix = p + (p>>4);
    float2 A = s_d[ix], B = s_d[ix+1];
    zr[2*c]   = A.x+B.x;  zi[2*c]   = A.y+B.y;   // freq ka
    zr[2*c+1] = A.x-B.x;  zi[2*c+1] = A.y-B.y;   // freq ka+512
  }
  __syncthreads();
  #pragma unroll
  for (int c=0;c<4;c++){
    int j  = tid + (c<<7);
    int ka = ((j&7)<<6) | (((j>>3)&7)<<3) | ((j>>6)&7);
    int kb = ka + 512;
    s_d[ka + (ka>>6)] = make_float2(zr[2*c],   zi[2*c]);
    s_d[kb + (kb>>6)] = make_float2(zr[2*c+1], zi[2*c+1]);
  }
  __syncthreads();

  // ---- unpack real-FFT magnitudes: k = 1 + tid + 128c (consecutive -> conflict-free) ----
  float mag = 0.f;
  {
    const float W128r =  0.92387953251128675613f;  // cos(-pi/8)
    const float W128i = -0.38268343236508977173f;  // sin(-pi/8)
    int k0 = 1 + tid;
    float wr, wi; __sincosf(-PI_F*(float)k0*(1.f/1024.f), &wi, &wr);
    #pragma unroll
    for (int c=0;c<4;c++){
      int k  = k0 + (c<<7);
      int k2 = 1024 - k;
      float2 Z1 = s_d[k  + (k >>6)];
      float2 Z2 = s_d[k2 + (k2>>6)];
      float Er = 0.5f*(Z1.x + Z2.x);
      float Ei = 0.5f*(Z1.y - Z2.y);
      float Or = 0.5f*(Z1.y + Z2.y);
      float Oi = 0.5f*(Z2.x - Z1.x);
      float Tr = wr*Or - wi*Oi;
      float Ti = wr*Oi + wi*Or;
      float n1 = (Er+Tr)*(Er+Tr) + (Ei+Ti)*(Ei+Ti);
      float n2 = (Er-Tr)*(Er-Tr) + (Ei-Ti)*(Ei-Ti);
      float m1 = n1*rsqrtf(fmaxf(n1,1e-30f));
      float m2 = n2*rsqrtf(fmaxf(n2,1e-30f));
      float sc = (k==512) ? 0.5f : 1.0f;
      mag += sc*(m1+m2);
      float nr,ni; cmul(wr,wi,W128r,W128i,nr,ni); wr=nr; wi=ni;
    }
    if (tid==0){
      float2 Z0 = s_d[0];   // k=0 slot
      mag += 0.5f*(fabsf(Z0.x+Z0.y) + fabsf(Z0.x-Z0.y));  // (|X0|+|X1024|)/2
    }
  }

  // ---- fused deterministic reductions (5-way), valid on tid 0 ----
  #pragma unroll
  for (int o=16;o;o>>=1){
    sm  += __shfl_xor_sync(0xffffffffu, sm,  o);
    sq  += __shfl_xor_sync(0xffffffffu, sq,  o);
    mag += __shfl_xor_sync(0xffffffffu, mag, o);
    mx   = fmaxf(mx, __shfl_xor_sync(0xffffffffu, mx, o));
    mn   = fminf(mn, __shfl_xor_sync(0xffffffffu, mn, o));
  }
  if (lane==0){
    scr[warp]=sm; scr[4+warp]=sq; scr[8+warp]=mag; scr[12+warp]=mx; scr[16+warp]=mn;
  }
  __syncthreads();
  float sm_t=0.f, sq_t=0.f, mag_t=0.f, mx_t=-3.0e38f, mn_t=3.0e38f;
  if (tid==0){
    #pragma unroll
    for (int i=0;i<4;i++){
      sm_t+=scr[i]; sq_t+=scr[4+i]; mag_t+=scr[8+i];
      mx_t=fmaxf(mx_t,scr[12+i]); mn_t=fminf(mn_t,scr[16+i]);
    }
  }

  // ================= peak/valley: contiguous 16-wide chunk per thread =================
  const int base = tid<<4;          // covers s[base .. base+17]
  float v[18];
  {
    const int sw = (tid>>1)&3;      // bank swizzle: kills 4-way conflicts on 64B-lane stride
    #pragma unroll
    for (int c=0;c<4;c++){
      int cc = (c + sw) & 3;
      float4 q = *(const float4*)&s_sig[base + (cc<<2)];
      v[4*cc]=q.x; v[4*cc+1]=q.y; v[4*cc+2]=q.z; v[4*cc+3]=q.w;
    }
    // tail: s[base+16], s[base+17] are next thread's v[0],v[1]
    float t0 = __shfl_down_sync(0xffffffffu, v[0], 1);
    float t1 = __shfl_down_sync(0xffffffffu, v[1], 1);
    if (lane==31){
      t0 = (base+16 < 2048) ? s_sig[base+16] : 0.f;
      t1 = (base+17 < 2048) ? s_sig[base+17] : 0.f;
    }
    v[16]=t0; v[17]=t1;
  }

  // Phase 1: counts, first peak, first/last valley; build valley mask
  unsigned vmask=0u;
  {
    int lnp=0, lnv=0, lp0=0x7fffffff, lv0=0x7fffffff, lvl=-1;
    #pragma unroll
    for (int j=0;j<16;j++){
      int i = base + j + 1;
      if (i<=2046){
        bool pk = (v[j]<v[j+1]) && (v[j+1]>v[j+2]);
        bool vl = (v[j]>v[j+1]) && (v[j+1]<v[j+2]);
        if (pk){ lnp++; lp0 = min(lp0,i); }
        if (vl){ lnv++; vmask |= (1u<<j); lv0 = min(lv0,i); lvl = max(lvl,i); }
      }
    }
    if (lnp) atomicAdd(&sh_np, lnp);
    if (lnv) atomicAdd(&sh_nv, lnv);
    if (lp0!=0x7fffffff) atomicMin(&sh_p0, lp0);
    if (lv0!=0x7fffffff){ atomicMin(&sh_v0, lv0); atomicMax(&sh_vl, lvl); }
  }
  __syncthreads();

  const int np = sh_np, nv = sh_nv;
  const int p0 = (sh_p0==0x7fffffff) ? 1 : sh_p0;
  const int v0 = (sh_v0==0x7fffffff) ? 1 : sh_v0;
  const int vlast = (sh_vl<0) ? 2046 : sh_vl;
  const float half = 0.5f*(s_sig[p0] + s_sig[v0]);

  // Phase 2: second valley (>v0), half-height crossings
  {
    int lv1=0x7fffffff, lli=0x7fffffff, lri=-1;
    #pragma unroll
    for (int j=0;j<16;j++){
      int i = base + j + 1;
      if ((vmask>>j)&1u){ if (i>v0) lv1 = min(lv1,i); }
      if (v[j+1]>=half){
        if (i>=v0 && i< p0) lli = min(lli,i);
        if (i> v0 && i<=p0) lri = max(lri,i);
      }
    }
    if (lv1!=0x7fffffff) atomicMin(&sh_v1, lv1);
    if (lli!=0x7fffffff) atomicMin(&sh_li, lli);
    if (lri>=0)          atomicMax(&sh_ri, lri);
  }
  __syncthreads();

  const int v1 = (sh_v1==0x7fffffff) ? 1  : sh_v1;
  const int li = (sh_li==0x7fffffff) ? v0 : sh_li;
  const int ri = (sh_ri<0)           ? p0 : sh_ri;

  // Phase 3: masked trapezoid sums; pair ip = base+j, pr = 0.5*(v[j]+v[j+1])
  float aPA=0.f, aA2=0.f, aA1=0.f;
  #pragma unroll
  for (int j=0;j<16;j++){
    int ip = base + j;
    if (ip<=2046){
      float pr = 0.5f*(v[j] + v[j+1]);
      if (ip>=v0 && ip<=vlast-2) aPA += pr;
      if (ip>=p0 && ip<=v1-2)    aA2 += pr;
      if (ip>=v0 && ip<=p0-2)    aA1 += pr;
    }
  }
  #pragma unroll
  for (int o=16;o;o>>=1){
    aPA += __shfl_xor_sync(0xffffffffu, aPA, o);
    aA2 += __shfl_xor_sync(0xffffffffu, aA2, o);
    aA1 += __shfl_xor_sync(0xffffffffu, aA1, o);
  }
  if (lane==0){ scr[warp]=aPA; scr[4+warp]=aA2; scr[8+warp]=aA1; }
  __syncthreads();

  // ---- write 10 features ----
  if (tid==0){
    float PA_t=0.f, A2_t=0.f, A1_t=0.f;
    #pragma unroll
    for (int i=0;i<4;i++){ PA_t+=scr[i]; A2_t+=scr[4+i]; A1_t+=scr[8+i]; }
    const float n = 2048.f;
    float var = (sq_t - sm_t*sm_t/n) / (n - 1.f);
    var = fmaxf(var, 0.f);
    float stdv = sqrtf(var);
    float mean_amp = (2.f*mag_t) / n;
    bool gate = (np>=1) && (nv>=2);
    float PA=0.f, A2=0.f, PH=0.f, A1=0.f, PW=0.f;
    if (gate){
      PA = PA_t / 30.0f;
      A2 = A2_t / 30.0f;
      A1 = A1_t / 30.0f;
      PH = s_sig[p0] - s_sig[v0];
      PW = (float)(ri - li) / 30.0f;
    }
    float* o = out + row*10;
    o[0]=mx_t; o[1]=mx_t-mn_t; o[2]=var; o[3]=stdv; o[4]=mean_amp;
    o[5]=PA;   o[6]=A2;        o[7]=PH;  o[8]=A1;   o[9]=PW;
  }
}

extern "C" void kernel_launch(void* const* d_in, const int* in_sizes, int n_in,
                              void* d_out, int out_size) {
  const float* x = (const float*)d_in[0];
  float* out = (float*)d_out;
  (void)in_sizes; (void)n_in; (void)out_size;
  feat_kernel<<<32768, 128>>>(x, out);
}

// round 5
// speedup vs baseline: 1.3720x; 1.3720x over previous
#include <cuda_runtime.h>

#define PI_F 3.14159265358979323846f
typedef unsigned long long u64;

static __device__ __forceinline__ void cmul(float ar,float ai,float br,float bi,float&cr,float&ci){
  cr = ar*br - ai*bi; ci = ar*bi + ai*br;
}

// ---- f32x2 packed helpers (Blackwell FFMA2 path) ----
static __device__ __forceinline__ u64 PK(float lo, float hi){
  u64 r; asm("mov.b64 %0,{%1,%2};":"=l"(r):"f"(lo),"f"(hi)); return r;
}
static __device__ __forceinline__ void UPK(u64 v, float&lo, float&hi){
  asm("mov.b64 {%0,%1},%2;":"=f"(lo),"=f"(hi):"l"(v));
}
static __device__ __forceinline__ u64 SWP(u64 v){
  u64 r; asm("{\n\t.reg .b32 a,b;\n\tmov.b64 {a,b},%1;\n\tmov.b64 %0,{b,a};\n\t}":"=l"(r):"l"(v)); return r;
}
static __device__ __forceinline__ u64 ADDX(u64 a,u64 b){
  u64 r; asm("add.rn.f32x2 %0,%1,%2;":"=l"(r):"l"(a),"l"(b)); return r;
}
static __device__ __forceinline__ u64 MULX(u64 a,u64 b){
  u64 r; asm("mul.rn.f32x2 %0,%1,%2;":"=l"(r):"l"(a),"l"(b)); return r;
}
static __device__ __forceinline__ u64 FMX(u64 a,u64 b,u64 c){
  u64 r; asm("fma.rn.f32x2 %0,%1,%2,%3;":"=l"(r):"l"(a),"l"(b),"l"(c)); return r;
}

#define C_NEG1 0xBF800000BF800000ULL  /* (-1,-1) */
#define C_P1M1 0xBF8000003F800000ULL  /* (+1,-1) */
#define C_M1P1 0x3F800000BF800000ULL  /* (-1,+1) */
#define C_CC   0x3F3504F33F3504F3ULL  /* ( C, C) */
#define C_CMC  0xBF3504F33F3504F3ULL  /* ( C,-C) */

// packed DFT-8: x[m] = (re,im) as f32x2; identical math to scalar dft8
static __device__ __forceinline__ void dft8p(u64 x[8]){
  u64 u0=ADDX(x[0],x[4]), u1=FMX(x[4],C_NEG1,x[0]);
  u64 u2=ADDX(x[2],x[6]), u3=FMX(x[6],C_NEG1,x[2]);
  u64 v0=ADDX(x[1],x[5]), v1=FMX(x[5],C_NEG1,x[1]);
  u64 v2=ADDX(x[3],x[7]), v3=FMX(x[7],C_NEG1,x[3]);
  u64 E0=ADDX(u0,u2),     E2=FMX(u2,C_NEG1,u0);
  u64 su3=SWP(u3);
  u64 E1=FMX(su3,C_P1M1,u1), E3=FMX(su3,C_M1P1,u1);
  u64 O0=ADDX(v0,v2),     O2=FMX(v2,C_NEG1,v0);
  u64 sv3=SWP(v3);
  u64 O1=FMX(sv3,C_P1M1,v1), O3=FMX(sv3,C_M1P1,v1);
  u64 t1=FMX(SWP(O1),C_P1M1,O1);      // (O1r+O1i, O1i-O1r)
  u64 w1=MULX(t1,C_CC);
  u64 sO2=SWP(O2);
  u64 t3=FMX(O3,C_M1P1,SWP(O3));      // (O3i-O3r, O3r+O3i)
  u64 w3=MULX(t3,C_CMC);
  x[0]=ADDX(E0,O0);  x[4]=FMX(O0,C_NEG1,E0);
  x[1]=ADDX(E1,w1);  x[5]=FMX(w1,C_NEG1,E1);
  x[2]=FMX(sO2,C_P1M1,E2); x[6]=FMX(sO2,C_M1P1,E2);
  x[3]=ADDX(E3,w3);  x[7]=FMX(w3,C_NEG1,E3);
}

// bits j (0..15) with lo <= base1+j <= hi
static __device__ __forceinline__ unsigned wmask(int lo, int hi, int base1){
  int jlo = lo - base1, jhi = hi - base1;
  jlo = max(jlo, 0); jhi = min(jhi, 15);
  if (jhi < jlo) return 0u;
  return (0xFFFFu << jlo) & (0xFFFFu >> (15 - jhi));
}

__global__ void __launch_bounds__(128, 8)
feat_kernel(const float* __restrict__ x, float* __restrict__ out)
{
  __shared__ __align__(16) float s_sig[2048];
  __shared__ __align__(16) float2 s_d[1088];  // pad i+(i>>4); k-layout pad k+(k>>6)
  __shared__ float scr[20];
  __shared__ float chunkP[128];
  __shared__ float warptot[4];
  __shared__ float qP[5];
  __shared__ int   iscr[20];
  __shared__ int   sh_np, sh_nv, sh_p0, sh_v0, sh_vl, sh_v1, sh_li, sh_ri;

  const int tid  = threadIdx.x;   // 0..127
  const int lane = tid & 31;
  const int warp = tid >> 5;
  const size_t row = blockIdx.x;
  const float* xp = x + row * 2048;

  // ---- load row ----
  {
    const float4* xv = (const float4*)xp;
    float4* sv = (float4*)s_sig;
    #pragma unroll
    for (int c=0;c<4;c++) sv[tid + (c<<7)] = xv[tid + (c<<7)];
  }
  __syncthreads();

  // ============ 1024-pt complex FFT of z_n = x[2n] + i x[2n+1], DIF 8,8,8,2 ============
  u64 X[8];
  float mx=-3.0e38f, mn=3.0e38f;
  u64 smv=0ULL, sqv=0ULL;

  // ---- pass 1 ----
  {
    const u64* zin = (const u64*)s_sig;
    #pragma unroll
    for (int m=0;m<8;m++){
      u64 z = zin[tid + (m<<7)];
      float zx,zy; UPK(z,zx,zy);
      mx=fmaxf(mx,fmaxf(zx,zy)); mn=fminf(mn,fminf(zx,zy));
      smv = ADDX(smv, z);
      sqv = FMX(z, z, sqv);
      X[m] = z;
    }
    dft8p(X);
    float sn,cs; __sincosf(-2.f*PI_F*(float)tid*(1.f/1024.f), &sn, &cs);
    const int ob = tid + (tid>>4);
    *(u64*)&s_d[ob] = X[0];
    float wr=cs, wi=sn;
    #pragma unroll
    for (int q=1;q<8;q++){
      float xr,xi; UPK(X[q],xr,xi);
      float rr,ii; cmul(xr,xi,wr,wi,rr,ii);
      s_d[ob + 136*q] = make_float2(rr,ii);
      float nr,ni; cmul(wr,wi,cs,sn,nr,ni); wr=nr; wi=ni;
    }
  }
  __syncthreads();

  // ---- pass 2 ----
  {
    const int sub = tid>>4, tt = tid&15;
    const int ob = 136*sub + tt;
    #pragma unroll
    for (int m=0;m<8;m++) X[m] = *(const u64*)&s_d[ob + 17*m];
    dft8p(X);
    float sn,cs; __sincosf(-2.f*PI_F*(float)tt*(1.f/128.f), &sn, &cs);
    float wr=cs, wi=sn;
    *(u64*)&s_d[ob] = X[0];
    #pragma unroll
    for (int q=1;q<8;q++){
      float xr,xi; UPK(X[q],xr,xi);
      float rr,ii; cmul(xr,xi,wr,wi,rr,ii);
      s_d[ob + 17*q] = make_float2(rr,ii);
      float nr,ni; cmul(wr,wi,cs,sn,nr,ni); wr=nr; wi=ni;
    }
  }
  __syncthreads();

  // ---- pass 3 (tt warp-uniform: warps 0-1 twiddle-free) ----
  {
    const int tt = tid>>6, sid = tid&63;
    const int ob = 17*sid + tt;
    #pragma unroll
    for (int m=0;m<8;m++) X[m] = *(const u64*)&s_d[ob + 2*m];
    dft8p(X);
    *(u64*)&s_d[ob] = X[0];
    if (tt==0){
      #pragma unroll
      for (int q=1;q<8;q++) *(u64*)&s_d[ob + 2*q] = X[q];
    } else {
      const float cs = 0.92387953251128675613f, sn = -0.38268343236508977173f;
      float wr=cs, wi=sn;
      #pragma unroll
      for (int q=1;q<8;q++){
        float xr,xi; UPK(X[q],xr,xi);
        float rr,ii; cmul(xr,xi,wr,wi,rr,ii);
        s_d[ob + 2*q] = make_float2(rr,ii);
        float nr,ni; cmul(wr,wi,cs,sn,nr,ni); wr=nr; wi=ni;
      }
    }
  }
  __syncthreads();

  // ---- pass 4: radix-2 pairs, packed; re-store in natural k order ----
  u64 zs[8];
  #pragma unroll
  for (int c=0;c<4;c++){
    int j = tid + (c<<7);
    int p = 2*j;
    int ix = p + (p>>4);
    u64 A = *(const u64*)&s_d[ix], B = *(const u64*)&s_d[ix+1];
    zs[2*c]   = ADDX(A,B);
    zs[2*c+1] = FMX(B,C_NEG1,A);
  }
  __syncthreads();
  #pragma unroll
  for (int c=0;c<4;c++){
    int j  = tid + (c<<7);
    int ka = ((j&7)<<6) | (((j>>3)&7)<<3) | ((j>>6)&7);
    int kb = ka + 512;
    *(u64*)&s_d[ka + (ka>>6)] = zs[2*c];
    *(u64*)&s_d[kb + (kb>>6)] = zs[2*c+1];
  }
  __syncthreads();

  // ---- unpack real-FFT magnitudes (0.5 factors folded out) ----
  float mag = 0.f;
  {
    const float W128r =  0.92387953251128675613f;
    const float W128i = -0.38268343236508977173f;
    int k0 = 1 + tid;
    float wr, wi; __sincosf(-PI_F*(float)k0*(1.f/1024.f), &wi, &wr);
    #pragma unroll
    for (int c=0;c<4;c++){
      int k  = k0 + (c<<7);
      int k2 = 1024 - k;
      float2 Z1 = s_d[k  + (k >>6)];
      float2 Z2 = s_d[k2 + (k2>>6)];
      float Er = Z1.x + Z2.x;
      float Ei = Z1.y - Z2.y;
      float Or = Z1.y + Z2.y;
      float Oi = Z2.x - Z1.x;
      float Tr = wr*Or - wi*Oi;
      float Ti = wr*Oi + wi*Or;
      float n1 = (Er+Tr)*(Er+Tr) + (Ei+Ti)*(Ei+Ti);
      float n2 = (Er-Tr)*(Er-Tr) + (Ei-Ti)*(Ei-Ti);
      float m1 = n1*rsqrtf(fmaxf(n1,1e-30f));
      float m2 = n2*rsqrtf(fmaxf(n2,1e-30f));
      float sc = (k==512) ? 0.5f : 1.0f;
      mag += sc*(m1+m2);
      float nr,ni; cmul(wr,wi,W128r,W128i,nr,ni); wr=nr; wi=ni;
    }
    if (tid==0){
      float2 Z0 = s_d[0];
      mag += fabsf(Z0.x+Z0.y) + fabsf(Z0.x-Z0.y);
    }
    mag *= 0.5f;
  }

  // ---- fused deterministic reductions (valid on tid 0) ----
  float sm, sq;
  { float a,b; UPK(smv,a,b); sm = a+b; UPK(sqv,a,b); sq = a+b; }
  #pragma unroll
  for (int o=16;o;o>>=1){
    sm  += __shfl_xor_sync(0xffffffffu, sm,  o);
    sq  += __shfl_xor_sync(0xffffffffu, sq,  o);
    mag += __shfl_xor_sync(0xffffffffu, mag, o);
    mx   = fmaxf(mx, __shfl_xor_sync(0xffffffffu, mx, o));
    mn   = fminf(mn, __shfl_xor_sync(0xffffffffu, mn, o));
  }
  if (lane==0){
    scr[warp]=sm; scr[4+warp]=sq; scr[8+warp]=mag; scr[12+warp]=mx; scr[16+warp]=mn;
  }
  __syncthreads();
  float sm_t=0.f, sq_t=0.f, mag_t=0.f, mx_t=-3.0e38f, mn_t=3.0e38f;
  if (tid==0){
    #pragma unroll
    for (int i=0;i<4;i++){
      sm_t+=scr[i]; sq_t+=scr[4+i]; mag_t+=scr[8+i];
      mx_t=fmaxf(mx_t,scr[12+i]); mn_t=fminf(mn_t,scr[16+i]);
    }
  }

  // ================= peak/valley: bitmask + window formulation =================
  const int base  = tid<<4;
  const int base1 = base+1;
  float v[18];
  {
    const int sw = (tid>>1)&3;
    #pragma unroll
    for (int c=0;c<4;c++){
      int cc = (c + sw) & 3;
      float4 q = *(const float4*)&s_sig[base + (cc<<2)];
      v[4*cc]=q.x; v[4*cc+1]=q.y; v[4*cc+2]=q.z; v[4*cc+3]=q.w;
    }
    float t0 = __shfl_down_sync(0xffffffffu, v[0], 1);
    float t1 = __shfl_down_sync(0xffffffffu, v[1], 1);
    if (lane==31){
      t0 = (base+16 < 2048) ? s_sig[base+16] : 0.f;
      t1 = (base+17 < 2048) ? s_sig[base+17] : 0.f;
    }
    v[16]=t0; v[17]=t1;
  }

  // Phase 1: masks, counts, first peak, first/last valley
  unsigned pm=0u, vm=0u;
  {
    bool cl[17], gl[17];
    #pragma unroll
    for (int j=0;j<17;j++){ cl[j] = v[j]<v[j+1]; gl[j] = v[j]>v[j+1]; }
    #pragma unroll
    for (int j=0;j<16;j++){
      if (cl[j] && gl[j+1]) pm |= (1u<<j);
      if (gl[j] && cl[j+1]) vm |= (1u<<j);
    }
    if (tid==127){ pm &= 0x3FFFu; vm &= 0x3FFFu; }
    int lnp=__popc(pm), lnv=__popc(vm);
    int lp0 = pm ? base1 + (__ffs(pm)-1) : 0x7fffffff;
    int lv0 = vm ? base1 + (__ffs(vm)-1) : 0x7fffffff;
    int lvl = vm ? base1 + (31-__clz(vm)) : -1;
    #pragma unroll
    for (int o=16;o;o>>=1){
      lnp += __shfl_xor_sync(0xffffffffu,lnp,o);
      lnv += __shfl_xor_sync(0xffffffffu,lnv,o);
      lp0  = min(lp0, __shfl_xor_sync(0xffffffffu,lp0,o));
      lv0  = min(lv0, __shfl_xor_sync(0xffffffffu,lv0,o));
      lvl  = max(lvl, __shfl_xor_sync(0xffffffffu,lvl,o));
    }
    if (lane==0){ iscr[warp]=lnp; iscr[4+warp]=lnv; iscr[8+warp]=lp0; iscr[12+warp]=lv0; iscr[16+warp]=lvl; }
  }
  __syncthreads();
  if (tid==0){
    int a=0,b=0,c2=0x7fffffff,d=0x7fffffff,e=-1;
    #pragma unroll
    for (int i=0;i<4;i++){
      a+=iscr[i]; b+=iscr[4+i];
      c2=min(c2,iscr[8+i]); d=min(d,iscr[12+i]); e=max(e,iscr[16+i]);
    }
    sh_np=a; sh_nv=b;
    sh_p0=(c2==0x7fffffff)?1:c2;
    sh_v0=(d==0x7fffffff)?1:d;
    sh_vl=(e<0)?2046:e;
  }
  __syncthreads();
  const int np=sh_np, nv=sh_nv, p0=sh_p0, v0=sh_v0, vlast=sh_vl;
  const float half = 0.5f*(s_sig[p0] + s_sig[v0]);

  // Phase 2: half-mask + windows; plus chunk prefix scan (independent)
  {
    unsigned hm=0u;
    #pragma unroll
    for (int j=0;j<16;j++) if (v[j+1]>=half) hm |= (1u<<j);

    unsigned wv = vm & wmask(v0+1, 2046, base1);
    int lv1 = wv ? base1 + (__ffs(wv)-1) : 0x7fffffff;
    unsigned wl = hm & wmask(v0, p0-1, base1);
    int lli = wl ? base1 + (__ffs(wl)-1) : 0x7fffffff;
    unsigned wrm = hm & wmask(v0+1, p0, base1);
    int lri = wrm ? base1 + (31-__clz(wrm)) : -1;
    #pragma unroll
    for (int o=16;o;o>>=1){
      lv1 = min(lv1, __shfl_xor_sync(0xffffffffu,lv1,o));
      lli = min(lli, __shfl_xor_sync(0xffffffffu,lli,o));
      lri = max(lri, __shfl_xor_sync(0xffffffffu,lri,o));
    }
    if (lane==0){ iscr[warp]=lv1; iscr[4+warp]=lli; iscr[8+warp]=lri; }

    // chunk sums + inclusive warp scan
    float ts = ((v[0]+v[1])+(v[2]+v[3])) + ((v[4]+v[5])+(v[6]+v[7]))
             + ((v[8]+v[9])+(v[10]+v[11])) + ((v[12]+v[13])+(v[14]+v[15]));
    float run = ts;
    #pragma unroll
    for (int o=1;o<32;o<<=1){
      float nb = __shfl_up_sync(0xffffffffu, run, o);
      if (lane>=o) run += nb;
    }
    if (lane==31) warptot[warp] = run;
    __syncthreads();
    float wb = 0.f;
    #pragma unroll
    for (int w=0;w<4;w++) if (w<warp) wb += warptot[w];
    chunkP[tid] = wb + run - ts;   // exclusive prefix: sum of s[0..base-1]
    if (tid==0){
      int a=0x7fffffff,b=0x7fffffff,c2=-1;
      #pragma unroll
      for (int i=0;i<4;i++){ a=min(a,iscr[i]); b=min(b,iscr[4+i]); c2=max(c2,iscr[8+i]); }
      sh_v1=(a==0x7fffffff)?1:a;
      sh_li=(b==0x7fffffff)?v0:b;
      sh_ri=(c2<0)?p0:c2;
    }
  }
  __syncthreads();
  const int v1 = sh_v1;

  // P[i] (inclusive prefix) queries for the 5 needed indices
  if (tid < 5){
    int i = v0;
    if      (tid==1) i = p0-2;
    else if (tid==2) i = p0;
    else if (tid==3) i = v1-2;
    else if (tid==4) i = vlast-2;
    if (i < 0) i = 0;
    float p = chunkP[i>>4];
    int b0 = i & ~15;
    #pragma unroll
    for (int t=0;t<16;t++){ if (b0+t<=i) p += s_sig[b0+t]; }
    qP[tid] = p;
  }
  __syncthreads();

  // ---- write 10 features ----
  if (tid==0){
    const int li = sh_li, ri = sh_ri;
    float Pv0=qP[0], Pp2=qP[1], Pp0=qP[2], Pv12=qP[3], Pvl2=qP[4];
    float sv0 = s_sig[v0], sp1 = s_sig[p0-1], sp0v = s_sig[p0];
    float sv11 = s_sig[v1-1], svl1 = s_sig[vlast-1];
    // T(a,b) = 0.5 s[a] + (P[b-2]-P[a]) + 0.5 s[b-1], empty if b-2 < a
    float A1r = (p0-2    >= v0) ? (0.5f*(sv0 + sp1)  + (Pp2  - Pv0)) : 0.f;
    float A2r = (v1-2    >= p0) ? (0.5f*(sp0v+ sv11) + (Pv12 - Pp0)) : 0.f;
    float PAr = (vlast-2 >= v0) ? (0.5f*(sv0 + svl1) + (Pvl2 - Pv0)) : 0.f;

    const float n = 2048.f;
    float var = (sq_t - sm_t*sm_t/n) / (n - 1.f);
    var = fmaxf(var, 0.f);
    float stdv = sqrtf(var);
    float mean_amp = (2.f*mag_t) / n;
    bool gate = (np>=1) && (nv>=2);
    float PA=0.f, A2=0.f, PH=0.f, A1=0.f, PW=0.f;
    if (gate){
      PA = PAr / 30.0f;
      A2 = A2r / 30.0f;
      A1 = A1r / 30.0f;
      PH = sp0v - sv0;
      PW = (float)(ri - li) / 30.0f;
    }
    float* o = out + row*10;
    o[0]=mx_t; o[1]=mx_t-mn_t; o[2]=var; o[3]=stdv; o[4]=mean_amp;
    o[5]=PA;   o[6]=A2;        o[7]=PH;  o[8]=A1;   o[9]=PW;
  }
}

extern "C" void kernel_launch(void* const* d_in, const int* in_sizes, int n_in,
                              void* d_out, int out_size) {
  const float* x = (const float*)d_in[0];
  float* out = (float*)d_out;
  (void)in_sizes; (void)n_in; (void)out_size;
  feat_kernel<<<32768, 128>>>(x, out);
}

// round 7
// speedup vs baseline: 1.4506x; 1.0573x over previous
#include <cuda_runtime.h>

#define PI_F 3.14159265358979323846f
typedef unsigned long long u64;

static __device__ __forceinline__ void cmul(float ar,float ai,float br,float bi,float&cr,float&ci){
  cr = ar*br - ai*bi; ci = ar*bi + ai*br;
}

// ---- f32x2 packed helpers ----
static __device__ __forceinline__ u64 PK2(float lo, float hi){
  u64 r; asm("mov.b64 %0,{%1,%2};":"=l"(r):"f"(lo),"f"(hi)); return r;
}
static __device__ __forceinline__ void UPK(u64 v, float&lo, float&hi){
  asm("mov.b64 {%0,%1},%2;":"=f"(lo),"=f"(hi):"l"(v));
}
static __device__ __forceinline__ u64 SWP(u64 v){
  u64 r; asm("{\n\t.reg .b32 a,b;\n\tmov.b64 {a,b},%1;\n\tmov.b64 %0,{b,a};\n\t}":"=l"(r):"l"(v)); return r;
}
static __device__ __forceinline__ u64 ADDX(u64 a,u64 b){
  u64 r; asm("add.rn.f32x2 %0,%1,%2;":"=l"(r):"l"(a),"l"(b)); return r;
}
static __device__ __forceinline__ u64 MULX(u64 a,u64 b){
  u64 r; asm("mul.rn.f32x2 %0,%1,%2;":"=l"(r):"l"(a),"l"(b)); return r;
}
static __device__ __forceinline__ u64 FMX(u64 a,u64 b,u64 c){
  u64 r; asm("fma.rn.f32x2 %0,%1,%2,%3;":"=l"(r):"l"(a),"l"(b),"l"(c)); return r;
}

#define C_NEG1 0xBF800000BF800000ULL  /* (-1,-1) */
#define C_P1M1 0xBF8000003F800000ULL  /* (+1,-1) */
#define C_M1P1 0x3F800000BF800000ULL  /* (-1,+1) */
#define C_CC   0x3F3504F33F3504F3ULL  /* ( C, C) */
#define C_CMC  0xBF3504F33F3504F3ULL  /* ( C,-C) */

// packed DFT-8
static __device__ __forceinline__ void dft8p(u64 x[8]){
  u64 u0=ADDX(x[0],x[4]), u1=FMX(x[4],C_NEG1,x[0]);
  u64 u2=ADDX(x[2],x[6]), u3=FMX(x[6],C_NEG1,x[2]);
  u64 v0=ADDX(x[1],x[5]), v1=FMX(x[5],C_NEG1,x[1]);
  u64 v2=ADDX(x[3],x[7]), v3=FMX(x[7],C_NEG1,x[3]);
  u64 E0=ADDX(u0,u2),     E2=FMX(u2,C_NEG1,u0);
  u64 su3=SWP(u3);
  u64 E1=FMX(su3,C_P1M1,u1), E3=FMX(su3,C_M1P1,u1);
  u64 O0=ADDX(v0,v2),     O2=FMX(v2,C_NEG1,v0);
  u64 sv3=SWP(v3);
  u64 O1=FMX(sv3,C_P1M1,v1), O3=FMX(sv3,C_M1P1,v1);
  u64 t1=FMX(SWP(O1),C_P1M1,O1);
  u64 w1=MULX(t1,C_CC);
  u64 sO2=SWP(O2);
  u64 t3=FMX(O3,C_M1P1,SWP(O3));
  u64 w3=MULX(t3,C_CMC);
  x[0]=ADDX(E0,O0);  x[4]=FMX(O0,C_NEG1,E0);
  x[1]=ADDX(E1,w1);  x[5]=FMX(w1,C_NEG1,E1);
  x[2]=FMX(sO2,C_P1M1,E2); x[6]=FMX(sO2,C_M1P1,E2);
  x[3]=ADDX(E3,w3);  x[7]=FMX(w3,C_NEG1,E3);
}

// swizzled slot for frequency k; conflict-free for consecutive-k reads and
// (64q + 8e + f)-pattern writes.  sigma(k) = (k&~7) | ((k + (k>>3)) & 7)
static __device__ __forceinline__ int sig_idx(int k){
  return (k & ~7) | ((k + (k>>3)) & 7);
}

// bits j (0..15) with lo <= base1+j <= hi
static __device__ __forceinline__ unsigned wmask(int lo, int hi, int base1){
  int jlo = lo - base1, jhi = hi - base1;
  jlo = max(jlo, 0); jhi = min(jhi, 15);
  if (jhi < jlo) return 0u;
  return (0xFFFFu << jlo) & (0xFFFFu >> (15 - jhi));
}

__global__ void __launch_bounds__(128, 8)
feat_kernel(const float* __restrict__ x, float* __restrict__ out)
{
  __shared__ __align__(16) float s_sig[2048];
  __shared__ __align__(16) float2 s_d[1088];  // passes 1-2: pad i+(i>>4); final: sigma(k)
  __shared__ float scr[20];
  __shared__ float chunkP[128];
  __shared__ float warptot[4];
  __shared__ float qP[5];
  __shared__ int   iscr[32];   // phase1: [0..19], phase2: [20..31] (disjoint -> no race)
  __shared__ int   sh_v1, sh_li, sh_ri;

  const int tid  = threadIdx.x;   // 0..127
  const int lane = tid & 31;
  const int warp = tid >> 5;
  const size_t row = blockIdx.x;
  const float* xp = x + row * 2048;

  // ---- load row ----
  {
    const float4* xv = (const float4*)xp;
    float4* sv = (float4*)s_sig;
    #pragma unroll
    for (int c=0;c<4;c++) sv[tid + (c<<7)] = xv[tid + (c<<7)];
  }
  __syncthreads();

  // ============ 1024-pt complex FFT of z_n = x[2n] + i x[2n+1], DIF 8,8,8,2 ============
  u64 X[8];
  float mx=-3.0e38f, mn=3.0e38f;
  u64 smv=0ULL, sqv=0ULL;

  // ---- pass 1 ----
  {
    const u64* zin = (const u64*)s_sig;
    #pragma unroll
    for (int m=0;m<8;m++){
      u64 z = zin[tid + (m<<7)];
      float zx,zy; UPK(z,zx,zy);
      mx=fmaxf(mx,fmaxf(zx,zy)); mn=fminf(mn,fminf(zx,zy));
      smv = ADDX(smv, z);
      sqv = FMX(z, z, sqv);
      X[m] = z;
    }
    dft8p(X);
    float sn,cs; __sincosf(-2.f*PI_F*(float)tid*(1.f/1024.f), &sn, &cs);
    const int ob = tid + (tid>>4);
    *(u64*)&s_d[ob] = X[0];
    float wr=cs, wi=sn;
    #pragma unroll
    for (int q=1;q<8;q++){
      float xr,xi; UPK(X[q],xr,xi);
      float rr,ii; cmul(xr,xi,wr,wi,rr,ii);
      s_d[ob + 136*q] = make_float2(rr,ii);
      float nr,ni; cmul(wr,wi,cs,sn,nr,ni); wr=nr; wi=ni;
    }
  }
  __syncthreads();

  // ---- pass 2 ----
  {
    const int sub = tid>>4, tt = tid&15;
    const int ob = 136*sub + tt;
    #pragma unroll
    for (int m=0;m<8;m++) X[m] = *(const u64*)&s_d[ob + 17*m];
    dft8p(X);
    float sn,cs; __sincosf(-2.f*PI_F*(float)tt*(1.f/128.f), &sn, &cs);
    float wr=cs, wi=sn;
    *(u64*)&s_d[ob] = X[0];
    #pragma unroll
    for (int q=1;q<8;q++){
      float xr,xi; UPK(X[q],xr,xi);
      float rr,ii; cmul(xr,xi,wr,wi,rr,ii);
      s_d[ob + 17*q] = make_float2(rr,ii);
      float nr,ni; cmul(wr,wi,cs,sn,nr,ni); wr=nr; wi=ni;
    }
  }
  __syncthreads();

  // ---- pass 3 + radix-2 (merged via shuffle, partner = tid^16) ----
  {
    const int tt  = (tid>>4)&1;
    const int sid = (tid&15) | ((tid>>5)<<4);   // 0..63
    const int ob  = 17*sid + tt;
    #pragma unroll
    for (int m=0;m<8;m++) X[m] = *(const u64*)&s_d[ob + 2*m];
    dft8p(X);
    if (tt){   // twiddle W16^q
      const float cs = 0.92387953251128675613f, sn = -0.38268343236508977173f;
      float wr=cs, wi=sn;
      #pragma unroll
      for (int q=1;q<8;q++){
        float xr,xi; UPK(X[q],xr,xi);
        float rr,ii; cmul(xr,xi,wr,wi,rr,ii);
        X[q] = PK2(rr,ii);
        float nr,ni; cmul(wr,wi,cs,sn,nr,ni); wr=nr; wi=ni;
      }
    }
    // radix-2: tt=0 holds A, tt=1 holds B; sum->k, diff->k+512
    u64 Y[8];
    #pragma unroll
    for (int q=0;q<8;q++){
      u64 other = __shfl_xor_sync(0xffffffffu, X[q], 16);
      Y[q] = tt ? FMX(X[q], C_NEG1, other)   // A - B
                : ADDX(X[q], other);         // A + B
    }
    __syncthreads();   // all pass-3 reads done before sigma-layout overwrite
    const int e = sid & 7, f = sid >> 3;
    const int s0 = (e<<3) | ((f+e)&7) | (tt<<9);
    #pragma unroll
    for (int q=0;q<8;q++) *(u64*)&s_d[s0 + (q<<6)] = Y[q];
  }
  __syncthreads();

  // ---- unpack real-FFT magnitudes (0.5 folded out) ----
  float mag = 0.f;
  {
    const float W128r =  0.92387953251128675613f;
    const float W128i = -0.38268343236508977173f;
    int k0 = 1 + tid;
    float wr, wi; __sincosf(-PI_F*(float)k0*(1.f/1024.f), &wi, &wr);
    #pragma unroll
    for (int c=0;c<4;c++){
      int k  = k0 + (c<<7);
      int k2 = 1024 - k;
      float2 Z1 = s_d[sig_idx(k)];
      float2 Z2 = s_d[sig_idx(k2)];
      float Er = Z1.x + Z2.x;
      float Ei = Z1.y - Z2.y;
      float Or = Z1.y + Z2.y;
      float Oi = Z2.x - Z1.x;
      float Tr = wr*Or - wi*Oi;
      float Ti = wr*Oi + wi*Or;
      float n1 = (Er+Tr)*(Er+Tr) + (Ei+Ti)*(Ei+Ti);
      float n2 = (Er-Tr)*(Er-Tr) + (Ei-Ti)*(Ei-Ti);
      float m1 = n1*rsqrtf(fmaxf(n1,1e-30f));
      float m2 = n2*rsqrtf(fmaxf(n2,1e-30f));
      float sc = (k==512) ? 0.5f : 1.0f;
      mag += sc*(m1+m2);
      float nr,ni; cmul(wr,wi,W128r,W128i,nr,ni); wr=nr; wi=ni;
    }
    if (tid==0){
      float2 Z0 = s_d[0];
      mag += fabsf(Z0.x+Z0.y) + fabsf(Z0.x-Z0.y);
    }
    mag *= 0.5f;
  }

  // ---- fused deterministic float reductions (valid on tid 0) ----
  float sm, sq;
  { float a,b; UPK(smv,a,b); sm = a+b; UPK(sqv,a,b); sq = a+b; }
  #pragma unroll
  for (int o=16;o;o>>=1){
    sm  += __shfl_xor_sync(0xffffffffu, sm,  o);
    sq  += __shfl_xor_sync(0xffffffffu, sq,  o);
    mag += __shfl_xor_sync(0xffffffffu, mag, o);
    mx   = fmaxf(mx, __shfl_xor_sync(0xffffffffu, mx, o));
    mn   = fminf(mn, __shfl_xor_sync(0xffffffffu, mn, o));
  }
  if (lane==0){
    scr[warp]=sm; scr[4+warp]=sq; scr[8+warp]=mag; scr[12+warp]=mx; scr[16+warp]=mn;
  }
  __syncthreads();
  float sm_t=0.f, sq_t=0.f, mag_t=0.f, mx_t=-3.0e38f, mn_t=3.0e38f;
  if (tid==0){
    #pragma unroll
    for (int i=0;i<4;i++){
      sm_t+=scr[i]; sq_t+=scr[4+i]; mag_t+=scr[8+i];
      mx_t=fmaxf(mx_t,scr[12+i]); mn_t=fminf(mn_t,scr[16+i]);
    }
  }

  // ================= peak/valley: bitmask + window formulation =================
  const int base  = tid<<4;
  const int base1 = base+1;
  float v[18];
  {
    const int sw = (tid>>1)&3;
    #pragma unroll
    for (int c=0;c<4;c++){
      int cc = (c + sw) & 3;
      float4 q = *(const float4*)&s_sig[base + (cc<<2)];
      v[4*cc]=q.x; v[4*cc+1]=q.y; v[4*cc+2]=q.z; v[4*cc+3]=q.w;
    }
    float t0 = __shfl_down_sync(0xffffffffu, v[0], 1);
    float t1 = __shfl_down_sync(0xffffffffu, v[1], 1);
    if (lane==31){
      t0 = (base+16 < 2048) ? s_sig[base+16] : 0.f;
      t1 = (base+17 < 2048) ? s_sig[base+17] : 0.f;
    }
    v[16]=t0; v[17]=t1;
  }

  // Phase 1: masks, counts, first peak, first/last valley (redux warp reductions)
  unsigned vm=0u;
  {
    unsigned pm=0u;
    bool cl[17], gl[17];
    #pragma unroll
    for (int j=0;j<17;j++){ cl[j] = v[j]<v[j+1]; gl[j] = v[j]>v[j+1]; }
    #pragma unroll
    for (int j=0;j<16;j++){
      if (cl[j] && gl[j+1]) pm |= (1u<<j);
      if (gl[j] && cl[j+1]) vm |= (1u<<j);
    }
    if (tid==127){ pm &= 0x3FFFu; vm &= 0x3FFFu; }
    int lnp = __reduce_add_sync(0xffffffffu, __popc(pm));
    int lnv = __reduce_add_sync(0xffffffffu, __popc(vm));
    int lp0 = __reduce_min_sync(0xffffffffu, pm ? base1 + (__ffs(pm)-1) : 0x7fffffff);
    int lv0 = __reduce_min_sync(0xffffffffu, vm ? base1 + (__ffs(vm)-1) : 0x7fffffff);
    int lvl = __reduce_max_sync(0xffffffffu, vm ? base1 + (31-__clz(vm)) : -1);
    if (lane==0){ iscr[warp]=lnp; iscr[4+warp]=lnv; iscr[8+warp]=lp0; iscr[12+warp]=lv0; iscr[16+warp]=lvl; }
  }
  __syncthreads();
  int np, nv, p0, v0, vlast;
  {
    int a = iscr[0]+iscr[1]+iscr[2]+iscr[3];
    int b = iscr[4]+iscr[5]+iscr[6]+iscr[7];
    int c2 = min(min(iscr[8],iscr[9]),  min(iscr[10],iscr[11]));
    int d  = min(min(iscr[12],iscr[13]),min(iscr[14],iscr[15]));
    int e  = max(max(iscr[16],iscr[17]),max(iscr[18],iscr[19]));
    np=a; nv=b;
    p0=(c2==0x7fffffff)?1:c2;
    v0=(d ==0x7fffffff)?1:d;
    vlast=(e<0)?2046:e;
  }
  const float half = 0.5f*(s_sig[p0] + s_sig[v0]);

  // Phase 2: half-mask windows + chunk prefix scan (writes DISJOINT iscr[20..31])
  {
    unsigned hm=0u;
    #pragma unroll
    for (int j=0;j<16;j++) if (v[j+1]>=half) hm |= (1u<<j);

    unsigned wv = vm & wmask(v0+1, 2046, base1);
    unsigned wl = hm & wmask(v0, p0-1, base1);
    unsigned wrm = hm & wmask(v0+1, p0, base1);
    int lv1 = __reduce_min_sync(0xffffffffu, wv  ? base1 + (__ffs(wv)-1) : 0x7fffffff);
    int lli = __reduce_min_sync(0xffffffffu, wl  ? base1 + (__ffs(wl)-1) : 0x7fffffff);
    int lri = __reduce_max_sync(0xffffffffu, wrm ? base1 + (31-__clz(wrm)) : -1);
    if (lane==0){ iscr[20+warp]=lv1; iscr[24+warp]=lli; iscr[28+warp]=lri; }

    // chunk sums + inclusive warp scan
    float ts = ((v[0]+v[1])+(v[2]+v[3])) + ((v[4]+v[5])+(v[6]+v[7]))
             + ((v[8]+v[9])+(v[10]+v[11])) + ((v[12]+v[13])+(v[14]+v[15]));
    float run = ts;
    #pragma unroll
    for (int o=1;o<32;o<<=1){
      float nb = __shfl_up_sync(0xffffffffu, run, o);
      if (lane>=o) run += nb;
    }
    if (lane==31) warptot[warp] = run;
    __syncthreads();
    float wb = 0.f;
    #pragma unroll
    for (int w=0;w<4;w++) if (w<warp) wb += warptot[w];
    chunkP[tid] = wb + run - ts;   // exclusive prefix: sum of s[0..base-1]
    if (tid==0){
      int a = min(min(iscr[20],iscr[21]),min(iscr[22],iscr[23]));
      int b = min(min(iscr[24],iscr[25]),min(iscr[26],iscr[27]));
      int c2= max(max(iscr[28],iscr[29]),max(iscr[30],iscr[31]));
      sh_v1=(a==0x7fffffff)?1:a;
      sh_li=(b==0x7fffffff)?v0:b;
      sh_ri=(c2<0)?p0:c2;
    }
  }
  __syncthreads();
  const int v1 = sh_v1;

  // P[i] (inclusive prefix) queries
  if (tid < 5){
    int i = v0;
    if      (tid==1) i = p0-2;
    else if (tid==2) i = p0;
    else if (tid==3) i = v1-2;
    else if (tid==4) i = vlast-2;
    if (i < 0) i = 0;
    float p = chunkP[i>>4];
    int b0 = i & ~15;
    #pragma unroll
    for (int t=0;t<16;t++){ if (b0+t<=i) p += s_sig[b0+t]; }
    qP[tid] = p;
  }
  __syncthreads();

  // ---- write 10 features ----
  if (tid==0){
    const int li = sh_li, ri = sh_ri;
    float Pv0=qP[0], Pp2=qP[1], Pp0=qP[2], Pv12=qP[3], Pvl2=qP[4];
    float sv0 = s_sig[v0], sp1 = s_sig[p0-1], sp0v = s_sig[p0];
    float sv11 = s_sig[v1-1], svl1 = s_sig[vlast-1];
    float A1r = (p0-2    >= v0) ? (0.5f*(sv0 + sp1)  + (Pp2  - Pv0)) : 0.f;
    float A2r = (v1-2    >= p0) ? (0.5f*(sp0v+ sv11) + (Pv12 - Pp0)) : 0.f;
    float PAr = (vlast-2 >= v0) ? (0.5f*(sv0 + svl1) + (Pvl2 - Pv0)) : 0.f;

    const float n = 2048.f;
    float var = (sq_t - sm_t*sm_t/n) / (n - 1.f);
    var = fmaxf(var, 0.f);
    float stdv = sqrtf(var);
    float mean_amp = (2.f*mag_t) / n;
    bool gate = (np>=1) && (nv>=2);
    float PA=0.f, A2=0.f, PH=0.f, A1=0.f, PW=0.f;
    if (gate){
      PA = PAr / 30.0f;
      A2 = A2r / 30.0f;
      A1 = A1r / 30.0f;
      PH = sp0v - sv0;
      PW = (float)(ri - li) / 30.0f;
    }
    float* o = out + row*10;
    o[0]=mx_t; o[1]=mx_t-mn_t; o[2]=var; o[3]=stdv; o[4]=mean_amp;
    o[5]=PA;   o[6]=A2;        o[7]=PH;  o[8]=A1;   o[9]=PW;
  }
}

extern "C" void kernel_launch(void* const* d_in, const int* in_sizes, int n_in,
                              void* d_out, int out_size) {
  const float* x = (const float*)d_in[0];
  float* out = (float*)d_out;
  (void)in_sizes; (void)n_in; (void)out_size;
  feat_kernel<<<32768, 128>>>(x, out);
}

// round 8
// speedup vs baseline: 1.5054x; 1.0378x over previous
#include <cuda_runtime.h>

#define PI_F 3.14159265358979323846f
typedef unsigned long long u64;

static __device__ __forceinline__ void cmul(float ar,float ai,float br,float bi,float&cr,float&ci){
  cr = ar*br - ai*bi; ci = ar*bi + ai*br;
}

// ---- f32x2 packed helpers ----
static __device__ __forceinline__ u64 PK2(float lo, float hi){
  u64 r; asm("mov.b64 %0,{%1,%2};":"=l"(r):"f"(lo),"f"(hi)); return r;
}
static __device__ __forceinline__ void UPK(u64 v, float&lo, float&hi){
  asm("mov.b64 {%0,%1},%2;":"=f"(lo),"=f"(hi):"l"(v));
}
static __device__ __forceinline__ u64 SWP(u64 v){
  u64 r; asm("{\n\t.reg .b32 a,b;\n\tmov.b64 {a,b},%1;\n\tmov.b64 %0,{b,a};\n\t}":"=l"(r):"l"(v)); return r;
}
static __device__ __forceinline__ u64 ADDX(u64 a,u64 b){
  u64 r; asm("add.rn.f32x2 %0,%1,%2;":"=l"(r):"l"(a),"l"(b)); return r;
}
static __device__ __forceinline__ u64 MULX(u64 a,u64 b){
  u64 r; asm("mul.rn.f32x2 %0,%1,%2;":"=l"(r):"l"(a),"l"(b)); return r;
}
static __device__ __forceinline__ u64 FMX(u64 a,u64 b,u64 c){
  u64 r; asm("fma.rn.f32x2 %0,%1,%2,%3;":"=l"(r):"l"(a),"l"(b),"l"(c)); return r;
}
static __device__ __forceinline__ float SQRTA(float x){
  float r; asm("sqrt.approx.f32 %0,%1;":"=f"(r):"f"(x)); return r;
}

#define C_NEG1 0xBF800000BF800000ULL  /* (-1,-1) */
#define C_P1M1 0xBF8000003F800000ULL  /* (+1,-1) */
#define C_M1P1 0x3F800000BF800000ULL  /* (-1,+1) */
#define C_CC   0x3F3504F33F3504F3ULL  /* ( C, C) */
#define C_CMC  0xBF3504F33F3504F3ULL  /* ( C,-C) */

// packed DFT-8
static __device__ __forceinline__ void dft8p(u64 x[8]){
  u64 u0=ADDX(x[0],x[4]), u1=FMX(x[4],C_NEG1,x[0]);
  u64 u2=ADDX(x[2],x[6]), u3=FMX(x[6],C_NEG1,x[2]);
  u64 v0=ADDX(x[1],x[5]), v1=FMX(x[5],C_NEG1,x[1]);
  u64 v2=ADDX(x[3],x[7]), v3=FMX(x[7],C_NEG1,x[3]);
  u64 E0=ADDX(u0,u2),     E2=FMX(u2,C_NEG1,u0);
  u64 su3=SWP(u3);
  u64 E1=FMX(su3,C_P1M1,u1), E3=FMX(su3,C_M1P1,u1);
  u64 O0=ADDX(v0,v2),     O2=FMX(v2,C_NEG1,v0);
  u64 sv3=SWP(v3);
  u64 O1=FMX(sv3,C_P1M1,v1), O3=FMX(sv3,C_M1P1,v1);
  u64 t1=FMX(SWP(O1),C_P1M1,O1);
  u64 w1=MULX(t1,C_CC);
  u64 sO2=SWP(O2);
  u64 t3=FMX(O3,C_M1P1,SWP(O3));
  u64 w3=MULX(t3,C_CMC);
  x[0]=ADDX(E0,O0);  x[4]=FMX(O0,C_NEG1,E0);
  x[1]=ADDX(E1,w1);  x[5]=FMX(w1,C_NEG1,E1);
  x[2]=FMX(sO2,C_P1M1,E2); x[6]=FMX(sO2,C_M1P1,E2);
  x[3]=ADDX(E3,w3);  x[7]=FMX(w3,C_NEG1,E3);
}

// swizzled slot for frequency k (conflict-free both for writes and consecutive-k reads)
static __device__ __forceinline__ int sig_idx(int k){
  return (k & ~7) | ((k + (k>>3)) & 7);
}

// bits j (0..15) with lo <= base1+j <= hi
static __device__ __forceinline__ unsigned wmask(int lo, int hi, int base1){
  int jlo = lo - base1, jhi = hi - base1;
  jlo = max(jlo, 0); jhi = min(jhi, 15);
  if (jhi < jlo) return 0u;
  return (0xFFFFu << jlo) & (0xFFFFu >> (15 - jhi));
}

// order-preserving float<->uint key (no NaNs in data)
static __device__ __forceinline__ unsigned okey(float x){
  unsigned u = __float_as_uint(x);
  return u ^ ((unsigned)(((int)u)>>31) | 0x80000000u);
}
static __device__ __forceinline__ float okey_inv(unsigned k){
  unsigned u = (k & 0x80000000u) ? (k ^ 0x80000000u) : ~k;
  return __uint_as_float(u);
}

__global__ void __launch_bounds__(128, 8)
feat_kernel(const float* __restrict__ x, float* __restrict__ out)
{
  __shared__ __align__(16) float s_sig[2048];
  __shared__ __align__(16) float2 s_d[1088];  // passes 1-2: pad i+(i>>4); final: sigma(k)
  __shared__ float scr[20];
  __shared__ float chunkP[128];
  __shared__ float warptot[4];
  __shared__ float qP[5];
  __shared__ int   iscr[32];   // phase1: [0..19], phase2: [20..31] (disjoint)
  __shared__ int   sh_v1, sh_li, sh_ri;

  const int tid  = threadIdx.x;   // 0..127
  const int lane = tid & 31;
  const int warp = tid >> 5;
  const size_t row = blockIdx.x;
  const float* xp = x + row * 2048;

  // ============ 1024-pt complex FFT of z_n = x[2n] + i x[2n+1], DIF 8,8,8,2 ============
  u64 X[8];
  float mx=-3.0e38f, mn=3.0e38f;
  u64 smv=0ULL, sqv=0ULL;

  // ---- pass 1: direct LDG.64 at FFT stride; mirror into s_sig ----
  {
    const u64* zin = (const u64*)xp;
    u64* ssg = (u64*)s_sig;
    #pragma unroll
    for (int m=0;m<8;m++){
      u64 z = zin[tid + (m<<7)];
      ssg[tid + (m<<7)] = z;
      float zx,zy; UPK(z,zx,zy);
      mx=fmaxf(mx,fmaxf(zx,zy)); mn=fminf(mn,fminf(zx,zy));
      smv = ADDX(smv, z);
      sqv = FMX(z, z, sqv);
      X[m] = z;
    }
    dft8p(X);
    float sn,cs; __sincosf(-2.f*PI_F*(float)tid*(1.f/1024.f), &sn, &cs);
    const int ob = tid + (tid>>4);
    *(u64*)&s_d[ob] = X[0];
    float wr=cs, wi=sn;
    #pragma unroll
    for (int q=1;q<8;q++){
      float xr,xi; UPK(X[q],xr,xi);
      float rr,ii; cmul(xr,xi,wr,wi,rr,ii);
      s_d[ob + 136*q] = make_float2(rr,ii);
      float nr,ni; cmul(wr,wi,cs,sn,nr,ni); wr=nr; wi=ni;
    }
  }
  __syncthreads();

  // ---- pass 2 ----
  {
    const int sub = tid>>4, tt = tid&15;
    const int ob = 136*sub + tt;
    #pragma unroll
    for (int m=0;m<8;m++) X[m] = *(const u64*)&s_d[ob + 17*m];
    dft8p(X);
    float sn,cs; __sincosf(-2.f*PI_F*(float)tt*(1.f/128.f), &sn, &cs);
    float wr=cs, wi=sn;
    *(u64*)&s_d[ob] = X[0];
    #pragma unroll
    for (int q=1;q<8;q++){
      float xr,xi; UPK(X[q],xr,xi);
      float rr,ii; cmul(xr,xi,wr,wi,rr,ii);
      s_d[ob + 17*q] = make_float2(rr,ii);
      float nr,ni; cmul(wr,wi,cs,sn,nr,ni); wr=nr; wi=ni;
    }
  }
  __syncthreads();

  // ---- pass 3 + radix-2 (shuffle partner tid^16); COMPILE-TIME W16^q twiddles ----
  {
    const int tt  = (tid>>4)&1;
    const int sid = (tid&15) | ((tid>>5)<<4);   // 0..63
    const int ob  = 17*sid + tt;
    #pragma unroll
    for (int m=0;m<8;m++) X[m] = *(const u64*)&s_d[ob + 2*m];
    dft8p(X);
    if (tt){   // X[q] *= W16^q, constants -> FFMA/FMUL with immediates
      const float WR[8] = {1.f,  0.92387953251128675613f,  0.70710678118654752440f,
                            0.38268343236508977173f, 0.f, -0.38268343236508977173f,
                           -0.70710678118654752440f, -0.92387953251128675613f};
      const float WI[8] = {0.f, -0.38268343236508977173f, -0.70710678118654752440f,
                           -0.92387953251128675613f, -1.f, -0.92387953251128675613f,
                           -0.70710678118654752440f, -0.38268343236508977173f};
      #pragma unroll
      for (int q=1;q<8;q++){
        float xr,xi; UPK(X[q],xr,xi);
        X[q] = PK2(xr*WR[q] - xi*WI[q], xr*WI[q] + xi*WR[q]);
      }
    }
    u64 Y[8];
    #pragma unroll
    for (int q=0;q<8;q++){
      u64 other = __shfl_xor_sync(0xffffffffu, X[q], 16);
      Y[q] = tt ? FMX(X[q], C_NEG1, other)   // A - B
                : ADDX(X[q], other);         // A + B
    }
    __syncthreads();   // pass-3 reads done before sigma-layout overwrite
    const int e = sid & 7, f = sid >> 3;
    const int s0 = (e<<3) | ((f+e)&7) | (tt<<9);
    #pragma unroll
    for (int q=0;q<8;q++) *(u64*)&s_d[s0 + (q<<6)] = Y[q];
  }
  __syncthreads();

  // ---- unpack real-FFT magnitudes ----
  float mag = 0.f;
  {
    const float W128r =  0.92387953251128675613f;
    const float W128i = -0.38268343236508977173f;
    int k0 = 1 + tid;
    float wr, wi; __sincosf(-PI_F*(float)k0*(1.f/1024.f), &wi, &wr);
    float lastpair = 0.f;
    #pragma unroll
    for (int c=0;c<4;c++){
      int k  = k0 + (c<<7);
      int k2 = 1024 - k;
      float2 Z1 = s_d[sig_idx(k)];
      float2 Z2 = s_d[sig_idx(k2)];
      float Er = Z1.x + Z2.x;
      float Ei = Z1.y - Z2.y;
      float Or = Z1.y + Z2.y;
      float Oi = Z2.x - Z1.x;
      float Tr = wr*Or - wi*Oi;
      float Ti = wr*Oi + wi*Or;
      float n1 = (Er+Tr)*(Er+Tr) + (Ei+Ti)*(Ei+Ti);
      float n2 = (Er-Tr)*(Er-Tr) + (Ei-Ti)*(Ei-Ti);
      float s12 = SQRTA(n1) + SQRTA(n2);
      mag += s12;
      if (c==3) lastpair = s12;
      float nr,ni; cmul(wr,wi,W128r,W128i,nr,ni); wr=nr; wi=ni;
    }
    if (tid==127) mag -= 0.5f*lastpair;   // k=512 is its own mirror: counted twice above
    if (tid==0){
      float2 Z0 = s_d[0];
      mag += fabsf(Z0.x+Z0.y) + fabsf(Z0.x-Z0.y);
    }
    mag *= 0.5f;
  }

  // ---- fused deterministic reductions (valid on tid 0) ----
  u64 ssq;
  {
    float a,b,sm0,sq0;
    UPK(smv,a,b); sm0 = a+b;
    UPK(sqv,a,b); sq0 = a+b;
    ssq = PK2(sm0, sq0);
  }
  #pragma unroll
  for (int o=16;o;o>>=1){
    ssq  = ADDX(ssq, __shfl_xor_sync(0xffffffffu, ssq, o));
    mag += __shfl_xor_sync(0xffffffffu, mag, o);
  }
  unsigned kx = __reduce_max_sync(0xffffffffu, okey(mx));
  unsigned kn = __reduce_min_sync(0xffffffffu, okey(mn));
  if (lane==0){
    float sm0,sq0; UPK(ssq,sm0,sq0);
    scr[warp]=sm0; scr[4+warp]=sq0; scr[8+warp]=mag;
    scr[12+warp]=okey_inv(kx); scr[16+warp]=okey_inv(kn);
  }
  __syncthreads();
  float sm_t=0.f, sq_t=0.f, mag_t=0.f, mx_t=-3.0e38f, mn_t=3.0e38f;
  if (tid==0){
    #pragma unroll
    for (int i=0;i<4;i++){
      sm_t+=scr[i]; sq_t+=scr[4+i]; mag_t+=scr[8+i];
      mx_t=fmaxf(mx_t,scr[12+i]); mn_t=fminf(mn_t,scr[16+i]);
    }
  }

  // ================= peak/valley: bitmask + window formulation =================
  const int base  = tid<<4;
  const int base1 = base+1;
  float v[18];
  {
    const int sw = (tid>>1)&3;
    #pragma unroll
    for (int c=0;c<4;c++){
      int cc = (c + sw) & 3;
      float4 q = *(const float4*)&s_sig[base + (cc<<2)];
      v[4*cc]=q.x; v[4*cc+1]=q.y; v[4*cc+2]=q.z; v[4*cc+3]=q.w;
    }
    float t0 = __shfl_down_sync(0xffffffffu, v[0], 1);
    float t1 = __shfl_down_sync(0xffffffffu, v[1], 1);
    if (lane==31){
      t0 = (base+16 < 2048) ? s_sig[base+16] : 0.f;
      t1 = (base+17 < 2048) ? s_sig[base+17] : 0.f;
    }
    v[16]=t0; v[17]=t1;
  }

  // Phase 1
  unsigned vm=0u;
  {
    unsigned pm=0u;
    bool cl[17], gl[17];
    #pragma unroll
    for (int j=0;j<17;j++){ cl[j] = v[j]<v[j+1]; gl[j] = v[j]>v[j+1]; }
    #pragma unroll
    for (int j=0;j<16;j++){
      if (cl[j] && gl[j+1]) pm |= (1u<<j);
      if (gl[j] && cl[j+1]) vm |= (1u<<j);
    }
    if (tid==127){ pm &= 0x3FFFu; vm &= 0x3FFFu; }
    int lnp = __reduce_add_sync(0xffffffffu, __popc(pm));
    int lnv = __reduce_add_sync(0xffffffffu, __popc(vm));
    int lp0 = __reduce_min_sync(0xffffffffu, pm ? base1 + (__ffs(pm)-1) : 0x7fffffff);
    int lv0 = __reduce_min_sync(0xffffffffu, vm ? base1 + (__ffs(vm)-1) : 0x7fffffff);
    int lvl = __reduce_max_sync(0xffffffffu, vm ? base1 + (31-__clz(vm)) : -1);
    if (lane==0){ iscr[warp]=lnp; iscr[4+warp]=lnv; iscr[8+warp]=lp0; iscr[12+warp]=lv0; iscr[16+warp]=lvl; }
  }
  __syncthreads();
  int np, nv, p0, v0, vlast;
  {
    int a = iscr[0]+iscr[1]+iscr[2]+iscr[3];
    int b = iscr[4]+iscr[5]+iscr[6]+iscr[7];
    int c2 = min(min(iscr[8],iscr[9]),  min(iscr[10],iscr[11]));
    int d  = min(min(iscr[12],iscr[13]),min(iscr[14],iscr[15]));
    int e  = max(max(iscr[16],iscr[17]),max(iscr[18],iscr[19]));
    np=a; nv=b;
    p0=(c2==0x7fffffff)?1:c2;
    v0=(d ==0x7fffffff)?1:d;
    vlast=(e<0)?2046:e;
  }
  const float half = 0.5f*(s_sig[p0] + s_sig[v0]);

  // Phase 2 (disjoint iscr[20..31])
  {
    unsigned hm=0u;
    #pragma unroll
    for (int j=0;j<16;j++) if (v[j+1]>=half) hm |= (1u<<j);

    unsigned wv = vm & wmask(v0+1, 2046, base1);
    unsigned wl = hm & wmask(v0, p0-1, base1);
    unsigned wrm = hm & wmask(v0+1, p0, base1);
    int lv1 = __reduce_min_sync(0xffffffffu, wv  ? base1 + (__ffs(wv)-1) : 0x7fffffff);
    int lli = __reduce_min_sync(0xffffffffu, wl  ? base1 + (__ffs(wl)-1) : 0x7fffffff);
    int lri = __reduce_max_sync(0xffffffffu, wrm ? base1 + (31-__clz(wrm)) : -1);
    if (lane==0){ iscr[20+warp]=lv1; iscr[24+warp]=lli; iscr[28+warp]=lri; }

    // chunk sums + inclusive warp scan
    float ts = ((v[0]+v[1])+(v[2]+v[3])) + ((v[4]+v[5])+(v[6]+v[7]))
             + ((v[8]+v[9])+(v[10]+v[11])) + ((v[12]+v[13])+(v[14]+v[15]));
    float run = ts;
    #pragma unroll
    for (int o=1;o<32;o<<=1){
      float nb = __shfl_up_sync(0xffffffffu, run, o);
      if (lane>=o) run += nb;
    }
    if (lane==31) warptot[warp] = run;
    __syncthreads();
    float wb = 0.f;
    #pragma unroll
    for (int w=0;w<4;w++) if (w<warp) wb += warptot[w];
    chunkP[tid] = wb + run - ts;   // exclusive prefix: sum of s[0..base-1]
    if (tid==0){
      int a = min(min(iscr[20],iscr[21]),min(iscr[22],iscr[23]));
      int b = min(min(iscr[24],iscr[25]),min(iscr[26],iscr[27]));
      int c2= max(max(iscr[28],iscr[29]),max(iscr[30],iscr[31]));
      sh_v1=(a==0x7fffffff)?1:a;
      sh_li=(b==0x7fffffff)?v0:b;
      sh_ri=(c2<0)?p0:c2;
    }
  }
  __syncthreads();
  const int v1 = sh_v1;

  // P[i] (inclusive prefix) queries
  if (tid < 5){
    int i = v0;
    if      (tid==1) i = p0-2;
    else if (tid==2) i = p0;
    else if (tid==3) i = v1-2;
    else if (tid==4) i = vlast-2;
    if (i < 0) i = 0;
    float p = chunkP[i>>4];
    int b0 = i & ~15;
    #pragma unroll
    for (int t=0;t<16;t++){ if (b0+t<=i) p += s_sig[b0+t]; }
    qP[tid] = p;
  }
  __syncthreads();

  // ---- write 10 features ----
  if (tid==0){
    const int li = sh_li, ri = sh_ri;
    float Pv0=qP[0], Pp2=qP[1], Pp0=qP[2], Pv12=qP[3], Pvl2=qP[4];
    float sv0 = s_sig[v0], sp1 = s_sig[p0-1], sp0v = s_sig[p0];
    float sv11 = s_sig[v1-1], svl1 = s_sig[vlast-1];
    float A1r = (p0-2    >= v0) ? (0.5f*(sv0 + sp1)  + (Pp2  - Pv0)) : 0.f;
    float A2r = (v1-2    >= p0) ? (0.5f*(sp0v+ sv11) + (Pv12 - Pp0)) : 0.f;
    float PAr = (vlast-2 >= v0) ? (0.5f*(sv0 + svl1) + (Pvl2 - Pv0)) : 0.f;

    const float n = 2048.f;
    float var = (sq_t - sm_t*sm_t/n) / (n - 1.f);
    var = fmaxf(var, 0.f);
    float stdv = sqrtf(var);
    float mean_amp = (2.f*mag_t) / n;
    bool gate = (np>=1) && (nv>=2);
    float PA=0.f, A2=0.f, PH=0.f, A1=0.f, PW=0.f;
    if (gate){
      PA = PAr / 30.0f;
      A2 = A2r / 30.0f;
      A1 = A1r / 30.0f;
      PH = sp0v - sv0;
      PW = (float)(ri - li) / 30.0f;
    }
    float* o = out + row*10;
    o[0]=mx_t; o[1]=mx_t-mn_t; o[2]=var; o[3]=stdv; o[4]=mean_amp;
    o[5]=PA;   o[6]=A2;        o[7]=PH;  o[8]=A1;   o[9]=PW;
  }
}

extern "C" void kernel_launch(void* const* d_in, const int* in_sizes, int n_in,
                              void* d_out, int out_size) {
  const float* x = (const float*)d_in[0];
  float* out = (float*)d_out;
  (void)in_sizes; (void)n_in; (void)out_size;
  feat_kernel<<<32768, 128>>>(x, out);
}